// round 6
// baseline (speedup 1.0000x reference)
#include <cuda_runtime.h>
#include <math.h>

#define Bsz 4
#define Tn  512
#define Dm  512
#define Hn  8
#define HSz 64
#define Lnum 8
#define Vn  32000
#define DFn 2048
#define NT  (Bsz*Tn)          // 2048 tokens
#define EPSf 1e-5f

// ---------------- scratch (static device memory; no allocations) ------------
__device__ float g_x   [NT*Dm];
__device__ float g_x2  [NT*Dm];
__device__ float g_xn  [NT*Dm];
__device__ float g_qkv [3*NT*Dm];
__device__ float g_attn[NT*Dm];
__device__ float g_scores[(size_t)Bsz*Hn*Tn*Tn];
__device__ float g_ff  [NT*DFn];
__device__ float g_lossrow[NT];
__device__ float g_logits_fb[(size_t)NT*Vn];   // fallback if d_out lacks logits space

// ---------------- kernels ---------------------------------------------------

__global__ void k_embed(const int* __restrict__ idx, const float* __restrict__ tok,
                        const float* __restrict__ pos, float* __restrict__ x) {
    int row = blockIdx.x;          // 0..NT-1  (= b*T + t)
    int t = row % Tn;
    int tk = idx[row];
    const float* te = tok + (size_t)tk * Dm;
    const float* pe = pos + (size_t)t  * Dm;
    float* xr = x + (size_t)row * Dm;
    for (int c = threadIdx.x; c < Dm; c += blockDim.x)
        xr[c] = te[c] + pe[c];
}

__global__ void k_layernorm(const float* __restrict__ x, const float* __restrict__ g,
                            const float* __restrict__ b, float* __restrict__ y) {
    __shared__ float s1[128], s2[128];
    int row = blockIdx.x;
    const float* xr = x + (size_t)row * Dm;
    float*       yr = y + (size_t)row * Dm;
    float v[4], sum = 0.f, sq = 0.f;
#pragma unroll
    for (int i = 0; i < 4; i++) {
        v[i] = xr[threadIdx.x + i*128];
        sum += v[i]; sq += v[i]*v[i];
    }
    s1[threadIdx.x] = sum; s2[threadIdx.x] = sq; __syncthreads();
    for (int off = 64; off > 0; off >>= 1) {
        if (threadIdx.x < off) { s1[threadIdx.x] += s1[threadIdx.x+off];
                                 s2[threadIdx.x] += s2[threadIdx.x+off]; }
        __syncthreads();
    }
    float mu  = s1[0] * (1.f/Dm);
    float var = s2[0] * (1.f/Dm) - mu*mu;
    float rstd = rsqrtf(var + EPSf);
#pragma unroll
    for (int i = 0; i < 4; i++) {
        int c = threadIdx.x + i*128;
        yr[c] = (v[i] - mu) * rstd * g[c] + b[c];
    }
}

// C[M,N] = A[M,K] @ W[K,N] (+bias[N]) (+res[M,N]).  M%64==0, N%64==0, K%16==0.
__global__ void k_gemm(const float* __restrict__ A, const float* __restrict__ W,
                       const float* __restrict__ bias, const float* __restrict__ res,
                       float* __restrict__ C, int M, int N, int K) {
    __shared__ float As[16][68];
    __shared__ float Ws[16][64];
    int bm = blockIdx.y * 64, bn = blockIdx.x * 64;
    int tx = threadIdx.x & 15, ty = threadIdx.x >> 4;
    float acc[4][4] = {};
    for (int k0 = 0; k0 < K; k0 += 16) {
#pragma unroll
        for (int i = 0; i < 4; i++) {
            int e = threadIdx.x + i*256;        // 0..1023
            int m = e >> 4, kk = e & 15;
            As[kk][m] = A[(size_t)(bm + m) * K + (k0 + kk)];
        }
#pragma unroll
        for (int i = 0; i < 4; i++) {
            int e = threadIdx.x + i*256;
            int kk = e >> 6, n = e & 63;
            Ws[kk][n] = W[(size_t)(k0 + kk) * N + (bn + n)];
        }
        __syncthreads();
#pragma unroll
        for (int kk = 0; kk < 16; kk++) {
            float a[4], bb[4];
#pragma unroll
            for (int i = 0; i < 4; i++) a[i]  = As[kk][ty*4 + i];
#pragma unroll
            for (int j = 0; j < 4; j++) bb[j] = Ws[kk][tx*4 + j];
#pragma unroll
            for (int i = 0; i < 4; i++)
#pragma unroll
                for (int j = 0; j < 4; j++)
                    acc[i][j] = fmaf(a[i], bb[j], acc[i][j]);
        }
        __syncthreads();
    }
#pragma unroll
    for (int i = 0; i < 4; i++) {
        int m = bm + ty*4 + i;
#pragma unroll
        for (int j = 0; j < 4; j++) {
            int n = bn + tx*4 + j;
            float v = acc[i][j];
            if (bias) v += bias[n];
            if (res)  v += res[(size_t)m * N + n];
            C[(size_t)m * N + n] = v;
        }
    }
}

// S[bh, t, s] = (Q . K) * HS^-0.5, with optional causal mask (s>t -> -1e30)
__global__ void k_attn_scores(const float* __restrict__ qkv, float* __restrict__ S,
                              int causal) {
    int bh = blockIdx.z, b = bh >> 3, h = bh & 7;
    int t0 = blockIdx.y * 64, s0 = blockIdx.x * 64;
    __shared__ float Qs[64][65], Ks[64][65];
    const float* Q  = qkv + (size_t)(b*Tn + t0) * Dm + h*HSz;
    const float* Kp = qkv + (size_t)NT*Dm + (size_t)(b*Tn + s0) * Dm + h*HSz;
#pragma unroll
    for (int i = 0; i < 16; i++) {
        int e = threadIdx.x + i*256;   // 0..4095
        int r = e >> 6, c = e & 63;
        Qs[r][c] = Q [(size_t)r * Dm + c];
        Ks[r][c] = Kp[(size_t)r * Dm + c];
    }
    __syncthreads();
    int tx = threadIdx.x & 15, ty = threadIdx.x >> 4;
    float acc[4][4] = {};
#pragma unroll
    for (int kk = 0; kk < 64; kk++) {
        float a[4], bb[4];
#pragma unroll
        for (int i = 0; i < 4; i++) a[i]  = Qs[ty*4 + i][kk];
#pragma unroll
        for (int j = 0; j < 4; j++) bb[j] = Ks[tx*4 + j][kk];
#pragma unroll
        for (int i = 0; i < 4; i++)
#pragma unroll
            for (int j = 0; j < 4; j++)
                acc[i][j] = fmaf(a[i], bb[j], acc[i][j]);
    }
    float* Sp = S + (size_t)bh * Tn * Tn;
#pragma unroll
    for (int i = 0; i < 4; i++) {
        int t = t0 + ty*4 + i;
#pragma unroll
        for (int j = 0; j < 4; j++) {
            int s = s0 + tx*4 + j;
            float v = acc[i][j] * 0.125f;           // HS^-0.5 = 1/8
            if (causal && s > t) v = -1e30f;
            Sp[(size_t)t * Tn + s] = v;
        }
    }
}

__global__ void k_softmax(float* __restrict__ S) {
    __shared__ float red[128];
    int row = blockIdx.x;
    float* r = S + (size_t)row * Tn;
    float v[4], mx = -1e38f;
#pragma unroll
    for (int i = 0; i < 4; i++) { v[i] = r[threadIdx.x + i*128]; mx = fmaxf(mx, v[i]); }
    red[threadIdx.x] = mx; __syncthreads();
    for (int off = 64; off > 0; off >>= 1) {
        if (threadIdx.x < off) red[threadIdx.x] = fmaxf(red[threadIdx.x], red[threadIdx.x+off]);
        __syncthreads();
    }
    mx = red[0]; __syncthreads();
    float s = 0.f;
#pragma unroll
    for (int i = 0; i < 4; i++) { v[i] = __expf(v[i] - mx); s += v[i]; }
    red[threadIdx.x] = s; __syncthreads();
    for (int off = 64; off > 0; off >>= 1) {
        if (threadIdx.x < off) red[threadIdx.x] += red[threadIdx.x+off];
        __syncthreads();
    }
    float inv = 1.f / red[0];
#pragma unroll
    for (int i = 0; i < 4; i++) r[threadIdx.x + i*128] = v[i] * inv;
}

// O[b, t, h*HS + d] = sum_s P[bh, t, s] * V[b, s, h*HS + d]
__global__ void k_attn_pv(const float* __restrict__ S, const float* __restrict__ qkv,
                          float* __restrict__ O) {
    int bh = blockIdx.y, b = bh >> 3, h = bh & 7;
    int t0 = blockIdx.x * 64;
    __shared__ float Ps[16][68];
    __shared__ float Vs[16][64];
    const float* Sp = S + (size_t)bh * Tn * Tn;
    const float* Vp = qkv + (size_t)2*NT*Dm + (size_t)b*Tn*Dm + h*HSz;
    int tx = threadIdx.x & 15, ty = threadIdx.x >> 4;
    float acc[4][4] = {};
    for (int s0 = 0; s0 < Tn; s0 += 16) {
#pragma unroll
        for (int i = 0; i < 4; i++) {
            int e = threadIdx.x + i*256;
            int m = e >> 4, kk = e & 15;
            Ps[kk][m] = Sp[(size_t)(t0 + m) * Tn + s0 + kk];
        }
#pragma unroll
        for (int i = 0; i < 4; i++) {
            int e = threadIdx.x + i*256;
            int kk = e >> 6, n = e & 63;
            Vs[kk][n] = Vp[(size_t)(s0 + kk) * Dm + n];
        }
        __syncthreads();
#pragma unroll
        for (int kk = 0; kk < 16; kk++) {
            float a[4], bb[4];
#pragma unroll
            for (int i = 0; i < 4; i++) a[i]  = Ps[kk][ty*4 + i];
#pragma unroll
            for (int j = 0; j < 4; j++) bb[j] = Vs[kk][tx*4 + j];
#pragma unroll
            for (int i = 0; i < 4; i++)
#pragma unroll
                for (int j = 0; j < 4; j++)
                    acc[i][j] = fmaf(a[i], bb[j], acc[i][j]);
        }
        __syncthreads();
    }
    float* Op = O + (size_t)b*Tn*Dm + h*HSz;
#pragma unroll
    for (int i = 0; i < 4; i++)
#pragma unroll
        for (int j = 0; j < 4; j++)
            Op[(size_t)(t0 + ty*4 + i) * Dm + tx*4 + j] = acc[i][j];
}

__global__ void k_gelu(float* __restrict__ x, int n) {
    int i = blockIdx.x * blockDim.x + threadIdx.x;
    if (i < n) {
        float v = x[i];
        x[i] = 0.5f * v * (1.f + erff(v * 0.70710678118654752f));
    }
}

__global__ void k_lossrow(const float* __restrict__ logits, const int* __restrict__ tgt,
                          float* __restrict__ lr) {
    __shared__ float red[256];
    int row = blockIdx.x;
    const float* l = logits + (size_t)row * Vn;
    float mx = -1e38f;
    for (int c = threadIdx.x; c < Vn; c += 256) mx = fmaxf(mx, l[c]);
    red[threadIdx.x] = mx; __syncthreads();
    for (int off = 128; off > 0; off >>= 1) {
        if (threadIdx.x < off) red[threadIdx.x] = fmaxf(red[threadIdx.x], red[threadIdx.x+off]);
        __syncthreads();
    }
    mx = red[0]; __syncthreads();
    float s = 0.f;
    for (int c = threadIdx.x; c < Vn; c += 256) s += __expf(l[c] - mx);
    red[threadIdx.x] = s; __syncthreads();
    for (int off = 128; off > 0; off >>= 1) {
        if (threadIdx.x < off) red[threadIdx.x] += red[threadIdx.x+off];
        __syncthreads();
    }
    if (threadIdx.x == 0)
        lr[row] = mx + logf(red[0]) - l[tgt[row]];
}

__global__ void k_lossreduce(const float* __restrict__ lr, float* __restrict__ out) {
    __shared__ float red[256];
    float s = 0.f;
    for (int i = threadIdx.x; i < NT; i += 256) s += lr[i];
    red[threadIdx.x] = s; __syncthreads();
    for (int off = 128; off > 0; off >>= 1) {
        if (threadIdx.x < off) red[threadIdx.x] += red[threadIdx.x+off];
        __syncthreads();
    }
    if (threadIdx.x == 0) *out = red[0] / (float)NT;
}

// ---------------- host ------------------------------------------------------

extern "C" void kernel_launch(void* const* d_in, const int* in_sizes, int n_in,
                              void* d_out, int out_size) {
    const int*   idx  = (const int*)  d_in[0];
    const int*   tgt  = (const int*)  d_in[1];
    const float* tok  = (const float*)d_in[2];
    const float* pos  = (const float*)d_in[3];
    const float* uqw  = (const float*)d_in[4];
    const float* uqb  = (const float*)d_in[5];
    const float* upw  = (const float*)d_in[6];
    const float* upb  = (const float*)d_in[7];
    const float* mqw  = (const float*)d_in[8];
    const float* mqb  = (const float*)d_in[9];
    const float* mpw  = (const float*)d_in[10];
    const float* mpb  = (const float*)d_in[11];
    const float* w1   = (const float*)d_in[12];
    const float* b1   = (const float*)d_in[13];
    const float* w2   = (const float*)d_in[14];
    const float* b2   = (const float*)d_in[15];
    const float* g1   = (const float*)d_in[16];
    const float* bb1  = (const float*)d_in[17];
    const float* g2   = (const float*)d_in[18];
    const float* bb2  = (const float*)d_in[19];
    const float* lnfg = (const float*)d_in[20];
    const float* lnfb = (const float*)d_in[21];
    const float* wout = (const float*)d_in[22];
    const float* bout = (const float*)d_in[23];

    float *x, *x2, *xn, *qkv, *attn, *scores, *ff, *lr, *lfb;
    cudaGetSymbolAddress((void**)&x,      g_x);
    cudaGetSymbolAddress((void**)&x2,     g_x2);
    cudaGetSymbolAddress((void**)&xn,     g_xn);
    cudaGetSymbolAddress((void**)&qkv,    g_qkv);
    cudaGetSymbolAddress((void**)&attn,   g_attn);
    cudaGetSymbolAddress((void**)&scores, g_scores);
    cudaGetSymbolAddress((void**)&ff,     g_ff);
    cudaGetSymbolAddress((void**)&lr,     g_lossrow);
    cudaGetSymbolAddress((void**)&lfb,    g_logits_fb);

    k_embed<<<NT, 128>>>(idx, tok, pos, x);

    for (int l = 0; l < Lnum; l++) {
        for (int half = 0; half < 2; half++) {
            const float* qw = (half == 0 ? uqw : mqw) + (size_t)l * 3 * Dm * Dm;
            const float* qb = (half == 0 ? uqb : mqb) + (size_t)l * 3 * Dm;
            const float* pw = (half == 0 ? upw : mpw) + (size_t)l * Dm * Dm;
            const float* pb = (half == 0 ? upb : mpb) + (size_t)l * Dm;
            int causal = half;   // first sub-block unmasked, second causal

            // x2 = x + MHA(LN1(x))
            k_layernorm<<<NT, 128>>>(x, g1 + (size_t)l*Dm, bb1 + (size_t)l*Dm, xn);
            for (int c = 0; c < 3; c++)
                k_gemm<<<dim3(Dm/64, NT/64), 256>>>(xn, qw + (size_t)c*Dm*Dm,
                                                    qb + (size_t)c*Dm, nullptr,
                                                    qkv + (size_t)c*NT*Dm, NT, Dm, Dm);
            k_attn_scores<<<dim3(Tn/64, Tn/64, Bsz*Hn), 256>>>(qkv, scores, causal);
            k_softmax<<<Bsz*Hn*Tn, 128>>>(scores);
            k_attn_pv<<<dim3(Tn/64, Bsz*Hn), 256>>>(scores, qkv, attn);
            k_gemm<<<dim3(Dm/64, NT/64), 256>>>(attn, pw, pb, x, x2, NT, Dm, Dm);

            // x = x2 + FF(LN2(x2))
            k_layernorm<<<NT, 128>>>(x2, g2 + (size_t)l*Dm, bb2 + (size_t)l*Dm, xn);
            k_gemm<<<dim3(DFn/64, NT/64), 256>>>(xn, w1 + (size_t)l*Dm*DFn,
                                                 b1 + (size_t)l*DFn, nullptr,
                                                 ff, NT, DFn, Dm);
            k_gelu<<<(NT*DFn + 255)/256, 256>>>(ff, NT*DFn);
            // FIXED: K = DFn (was Dm in R1-R4 — the bug behind rel_err 1.35)
            k_gemm<<<dim3(Dm/64, NT/64), 256>>>(ff, w2 + (size_t)l*DFn*Dm,
                                                b2 + (size_t)l*Dm, x2, x, NT, Dm, DFn);
        }
    }

    // final LN + logits + loss
    k_layernorm<<<NT, 128>>>(x, lnfg, lnfb, xn);

    long long total = (long long)NT * Vn;
    float* logits = ((long long)out_size >= total) ? (float*)d_out : lfb;
    k_gemm<<<dim3(Vn/64, NT/64), 256>>>(xn, wout, bout, nullptr, logits, NT, Vn, Dm);

    k_lossrow<<<NT, 256>>>(logits, tgt, lr);

    float* lossdst;
    if ((long long)out_size >= total + 1)      lossdst = (float*)d_out + total;
    else if ((long long)out_size < total)      lossdst = (float*)d_out;  // loss-only layout
    else                                       lossdst = lr;             // logits-only: keep loss in scratch
    k_lossreduce<<<1, 256>>>(lr, lossdst);
}

// round 7
// speedup vs baseline: 1.0514x; 1.0514x over previous
#include <cuda_runtime.h>
#include <math.h>

#define Bsz 4
#define Tn  512
#define Dm  512
#define Hn  8
#define HSz 64
#define Lnum 8
#define Vn  32000
#define DFn 2048
#define NT  (Bsz*Tn)          // 2048 tokens
#define EPSf 1e-5f

// ---------------- scratch ----------------------------------------------------
__device__ float g_x   [NT*Dm];
__device__ float g_x2  [NT*Dm];
__device__ float g_xn  [NT*Dm];
__device__ float g_qkv [3*NT*Dm];
__device__ float g_attn[NT*Dm];
__device__ float g_scores[(size_t)Bsz*Hn*Tn*Tn];
__device__ float g_ff  [NT*DFn];
__device__ float g_lossrow[NT];
__device__ float g_logits_fb[(size_t)NT*Vn];

// ---------------- small kernels ---------------------------------------------

__global__ void k_embed(const int* __restrict__ idx, const float* __restrict__ tok,
                        const float* __restrict__ pos, float* __restrict__ x) {
    int row = blockIdx.x;
    int t = row % Tn;
    int tk = idx[row];
    const float* te = tok + (size_t)tk * Dm;
    const float* pe = pos + (size_t)t  * Dm;
    float* xr = x + (size_t)row * Dm;
    for (int c = threadIdx.x; c < Dm; c += blockDim.x)
        xr[c] = te[c] + pe[c];
}

__global__ void k_layernorm(const float* __restrict__ x, const float* __restrict__ g,
                            const float* __restrict__ b, float* __restrict__ y) {
    __shared__ float s1[128], s2[128];
    int row = blockIdx.x;
    const float* xr = x + (size_t)row * Dm;
    float*       yr = y + (size_t)row * Dm;
    float v[4], sum = 0.f, sq = 0.f;
#pragma unroll
    for (int i = 0; i < 4; i++) {
        v[i] = xr[threadIdx.x + i*128];
        sum += v[i]; sq += v[i]*v[i];
    }
    s1[threadIdx.x] = sum; s2[threadIdx.x] = sq; __syncthreads();
    for (int off = 64; off > 0; off >>= 1) {
        if (threadIdx.x < off) { s1[threadIdx.x] += s1[threadIdx.x+off];
                                 s2[threadIdx.x] += s2[threadIdx.x+off]; }
        __syncthreads();
    }
    float mu  = s1[0] * (1.f/Dm);
    float var = s2[0] * (1.f/Dm) - mu*mu;
    float rstd = rsqrtf(var + EPSf);
#pragma unroll
    for (int i = 0; i < 4; i++) {
        int c = threadIdx.x + i*128;
        yr[c] = (v[i] - mu) * rstd * g[c] + b[c];
    }
}

__device__ __forceinline__ float gelu_f(float v) {
    return 0.5f * v * (1.f + erff(v * 0.70710678118654752f));
}

// ---------------- big GEMM: 128x128x16, 256 thr, 8x8 micro, double-buffered --
// C[M,N] = A[M,K] @ W[K,N] + bias (+gelu). M%128==0, N%128==0, K%16==0.
__global__ __launch_bounds__(256) void k_gemm_big(
    const float* __restrict__ A, const float* __restrict__ W,
    const float* __restrict__ bias, float* __restrict__ C,
    int M, int N, int K, int gelu) {
    __shared__ float As[2][16][132];
    __shared__ float Ws[2][16][132];
    int bm = blockIdx.y * 128, bn = blockIdx.x * 128;
    int tid = threadIdx.x;
    int tx = tid & 15, ty = tid >> 4;

    // load indices
    int p0 = tid, p1 = tid + 256;
    int ar0 = p0 >> 2, ac0 = (p0 & 3) * 4;
    int ar1 = p1 >> 2, ac1 = (p1 & 3) * 4;
    int wk0 = p0 >> 5, wn0 = (p0 & 31) * 4;
    int wk1 = p1 >> 5, wn1 = (p1 & 31) * 4;

    const float* Ap0 = A + (size_t)(bm + ar0) * K + ac0;
    const float* Ap1 = A + (size_t)(bm + ar1) * K + ac1;
    const float* Wp0 = W + (size_t)wk0 * N + bn + wn0;
    const float* Wp1 = W + (size_t)wk1 * N + bn + wn1;

    float acc[8][8] = {};
    float4 ra0, ra1, rw0, rw1;

    // prologue: tile 0
    ra0 = *(const float4*)Ap0;
    ra1 = *(const float4*)Ap1;
    rw0 = *(const float4*)Wp0;
    rw1 = *(const float4*)Wp1;
    {
        As[0][ac0+0][ar0]=ra0.x; As[0][ac0+1][ar0]=ra0.y; As[0][ac0+2][ar0]=ra0.z; As[0][ac0+3][ar0]=ra0.w;
        As[0][ac1+0][ar1]=ra1.x; As[0][ac1+1][ar1]=ra1.y; As[0][ac1+2][ar1]=ra1.z; As[0][ac1+3][ar1]=ra1.w;
        *(float4*)&Ws[0][wk0][wn0] = rw0;
        *(float4*)&Ws[0][wk1][wn1] = rw1;
    }
    __syncthreads();

    int nt = K / 16;
    for (int t = 0; t < nt; t++) {
        int buf = t & 1;
        if (t + 1 < nt) {
            int k0 = (t + 1) * 16;
            ra0 = *(const float4*)(Ap0 + k0);
            ra1 = *(const float4*)(Ap1 + k0);
            rw0 = *(const float4*)(Wp0 + (size_t)k0 * N);
            rw1 = *(const float4*)(Wp1 + (size_t)k0 * N);
        }
#pragma unroll
        for (int kk = 0; kk < 16; kk++) {
            float4 a0 = *(const float4*)&As[buf][kk][ty*8];
            float4 a1 = *(const float4*)&As[buf][kk][ty*8+4];
            float4 b0 = *(const float4*)&Ws[buf][kk][tx*8];
            float4 b1 = *(const float4*)&Ws[buf][kk][tx*8+4];
            float a[8] = {a0.x,a0.y,a0.z,a0.w,a1.x,a1.y,a1.z,a1.w};
            float b[8] = {b0.x,b0.y,b0.z,b0.w,b1.x,b1.y,b1.z,b1.w};
#pragma unroll
            for (int i = 0; i < 8; i++)
#pragma unroll
                for (int j = 0; j < 8; j++)
                    acc[i][j] = fmaf(a[i], b[j], acc[i][j]);
        }
        if (t + 1 < nt) {
            int nb = (t + 1) & 1;
            As[nb][ac0+0][ar0]=ra0.x; As[nb][ac0+1][ar0]=ra0.y; As[nb][ac0+2][ar0]=ra0.z; As[nb][ac0+3][ar0]=ra0.w;
            As[nb][ac1+0][ar1]=ra1.x; As[nb][ac1+1][ar1]=ra1.y; As[nb][ac1+2][ar1]=ra1.z; As[nb][ac1+3][ar1]=ra1.w;
            *(float4*)&Ws[nb][wk0][wn0] = rw0;
            *(float4*)&Ws[nb][wk1][wn1] = rw1;
            __syncthreads();
        }
    }

#pragma unroll
    for (int i = 0; i < 8; i++) {
        int m = bm + ty*8 + i;
#pragma unroll
        for (int j = 0; j < 8; j++) {
            int n = bn + tx*8 + j;
            float v = acc[i][j] + bias[n];
            if (gelu) v = gelu_f(v);
            C[(size_t)m * N + n] = v;
        }
    }
}

// ---------------- small GEMM: 64x64x16, 128 thr, 8x4 micro, double-buffered --
// grid.z batching: W += z*wz, bias += z*bz, C += z*cz. (+res, N%64, K%16)
__global__ __launch_bounds__(128) void k_gemm_small(
    const float* __restrict__ A, const float* __restrict__ W,
    const float* __restrict__ bias, const float* __restrict__ res,
    float* __restrict__ C, int M, int N, int K,
    long long wz, long long bz, long long cz) {
    W    += (size_t)blockIdx.z * wz;
    bias += (size_t)blockIdx.z * bz;
    C    += (size_t)blockIdx.z * cz;

    __shared__ float As[2][16][68];
    __shared__ float Ws[2][16][68];
    int bm = blockIdx.y * 64, bn = blockIdx.x * 64;
    int tid = threadIdx.x;
    int tx = tid & 15, ty = tid >> 4;

    int p0 = tid, p1 = tid + 128;
    int ar0 = p0 >> 2, ac0 = (p0 & 3) * 4;
    int ar1 = p1 >> 2, ac1 = (p1 & 3) * 4;
    int wk0 = p0 >> 4, wn0 = (p0 & 15) * 4;
    int wk1 = p1 >> 4, wn1 = (p1 & 15) * 4;

    const float* Ap0 = A + (size_t)(bm + ar0) * K + ac0;
    const float* Ap1 = A + (size_t)(bm + ar1) * K + ac1;
    const float* Wp0 = W + (size_t)wk0 * N + bn + wn0;
    const float* Wp1 = W + (size_t)wk1 * N + bn + wn1;

    float acc[8][4] = {};
    float4 ra0, ra1, rw0, rw1;

    ra0 = *(const float4*)Ap0;
    ra1 = *(const float4*)Ap1;
    rw0 = *(const float4*)Wp0;
    rw1 = *(const float4*)Wp1;
    {
        As[0][ac0+0][ar0]=ra0.x; As[0][ac0+1][ar0]=ra0.y; As[0][ac0+2][ar0]=ra0.z; As[0][ac0+3][ar0]=ra0.w;
        As[0][ac1+0][ar1]=ra1.x; As[0][ac1+1][ar1]=ra1.y; As[0][ac1+2][ar1]=ra1.z; As[0][ac1+3][ar1]=ra1.w;
        *(float4*)&Ws[0][wk0][wn0] = rw0;
        *(float4*)&Ws[0][wk1][wn1] = rw1;
    }
    __syncthreads();

    int nt = K / 16;
    for (int t = 0; t < nt; t++) {
        int buf = t & 1;
        if (t + 1 < nt) {
            int k0 = (t + 1) * 16;
            ra0 = *(const float4*)(Ap0 + k0);
            ra1 = *(const float4*)(Ap1 + k0);
            rw0 = *(const float4*)(Wp0 + (size_t)k0 * N);
            rw1 = *(const float4*)(Wp1 + (size_t)k0 * N);
        }
#pragma unroll
        for (int kk = 0; kk < 16; kk++) {
            float4 a0 = *(const float4*)&As[buf][kk][ty*8];
            float4 a1 = *(const float4*)&As[buf][kk][ty*8+4];
            float4 b0 = *(const float4*)&Ws[buf][kk][tx*4];
            float a[8] = {a0.x,a0.y,a0.z,a0.w,a1.x,a1.y,a1.z,a1.w};
            float b[4] = {b0.x,b0.y,b0.z,b0.w};
#pragma unroll
            for (int i = 0; i < 8; i++)
#pragma unroll
                for (int j = 0; j < 4; j++)
                    acc[i][j] = fmaf(a[i], b[j], acc[i][j]);
        }
        if (t + 1 < nt) {
            int nb = (t + 1) & 1;
            As[nb][ac0+0][ar0]=ra0.x; As[nb][ac0+1][ar0]=ra0.y; As[nb][ac0+2][ar0]=ra0.z; As[nb][ac0+3][ar0]=ra0.w;
            As[nb][ac1+0][ar1]=ra1.x; As[nb][ac1+1][ar1]=ra1.y; As[nb][ac1+2][ar1]=ra1.z; As[nb][ac1+3][ar1]=ra1.w;
            *(float4*)&Ws[nb][wk0][wn0] = rw0;
            *(float4*)&Ws[nb][wk1][wn1] = rw1;
            __syncthreads();
        }
    }

#pragma unroll
    for (int i = 0; i < 8; i++) {
        int m = bm + ty*8 + i;
#pragma unroll
        for (int j = 0; j < 4; j++) {
            int n = bn + tx*4 + j;
            float v = acc[i][j] + bias[n];
            if (res) v += res[(size_t)m * N + n];
            C[(size_t)m * N + n] = v;
        }
    }
}

// ---------------- attention --------------------------------------------------
// scores: transposed smem tiles, float4 fragments, 4x4 micro
__global__ __launch_bounds__(256) void k_attn_scores(
    const float* __restrict__ qkv, float* __restrict__ S, int causal) {
    int bh = blockIdx.z, b = bh >> 3, h = bh & 7;
    int t0 = blockIdx.y * 64, s0 = blockIdx.x * 64;
    __shared__ float Qs[64][68], Ks[64][68];   // [feature][row]
    const float* Q  = qkv + (size_t)(b*Tn + t0) * Dm + h*HSz;
    const float* Kp = qkv + (size_t)NT*Dm + (size_t)(b*Tn + s0) * Dm + h*HSz;
    int tid = threadIdx.x;
#pragma unroll
    for (int i = 0; i < 4; i++) {
        int p = tid + i*256;           // 0..1023 float4 slots
        int r = p >> 4, c4 = (p & 15) * 4;
        float4 q = *(const float4*)&Q [(size_t)r * Dm + c4];
        float4 k = *(const float4*)&Kp[(size_t)r * Dm + c4];
        Qs[c4+0][r]=q.x; Qs[c4+1][r]=q.y; Qs[c4+2][r]=q.z; Qs[c4+3][r]=q.w;
        Ks[c4+0][r]=k.x; Ks[c4+1][r]=k.y; Ks[c4+2][r]=k.z; Ks[c4+3][r]=k.w;
    }
    __syncthreads();
    int tx = tid & 15, ty = tid >> 4;
    float acc[4][4] = {};
#pragma unroll
    for (int kk = 0; kk < 64; kk++) {
        float4 a4 = *(const float4*)&Qs[kk][ty*4];
        float4 b4 = *(const float4*)&Ks[kk][tx*4];
        float a[4] = {a4.x,a4.y,a4.z,a4.w};
        float b[4] = {b4.x,b4.y,b4.z,b4.w};
#pragma unroll
        for (int i = 0; i < 4; i++)
#pragma unroll
            for (int j = 0; j < 4; j++)
                acc[i][j] = fmaf(a[i], b[j], acc[i][j]);
    }
    float* Sp = S + (size_t)bh * Tn * Tn;
#pragma unroll
    for (int i = 0; i < 4; i++) {
        int t = t0 + ty*4 + i;
#pragma unroll
        for (int j = 0; j < 4; j++) {
            int s = s0 + tx*4 + j;
            float v = acc[i][j] * 0.125f;
            if (causal && s > t) v = -1e30f;
            Sp[(size_t)t * Tn + s] = v;
        }
    }
}

__global__ void k_softmax(float* __restrict__ S) {
    __shared__ float red[128];
    int row = blockIdx.x;
    float* r = S + (size_t)row * Tn;
    float v[4], mx = -1e38f;
#pragma unroll
    for (int i = 0; i < 4; i++) { v[i] = r[threadIdx.x + i*128]; mx = fmaxf(mx, v[i]); }
    red[threadIdx.x] = mx; __syncthreads();
    for (int off = 64; off > 0; off >>= 1) {
        if (threadIdx.x < off) red[threadIdx.x] = fmaxf(red[threadIdx.x], red[threadIdx.x+off]);
        __syncthreads();
    }
    mx = red[0]; __syncthreads();
    float s = 0.f;
#pragma unroll
    for (int i = 0; i < 4; i++) { v[i] = __expf(v[i] - mx); s += v[i]; }
    red[threadIdx.x] = s; __syncthreads();
    for (int off = 64; off > 0; off >>= 1) {
        if (threadIdx.x < off) red[threadIdx.x] += red[threadIdx.x+off];
        __syncthreads();
    }
    float inv = 1.f / red[0];
#pragma unroll
    for (int i = 0; i < 4; i++) r[threadIdx.x + i*128] = v[i] * inv;
}

__global__ __launch_bounds__(256) void k_attn_pv(
    const float* __restrict__ S, const float* __restrict__ qkv,
    float* __restrict__ O) {
    int bh = blockIdx.y, b = bh >> 3, h = bh & 7;
    int t0 = blockIdx.x * 64;
    __shared__ float Ps[16][68];
    __shared__ float Vs[16][68];
    const float* Sp = S + (size_t)bh * Tn * Tn;
    const float* Vp = qkv + (size_t)2*NT*Dm + (size_t)b*Tn*Dm + h*HSz;
    int tx = threadIdx.x & 15, ty = threadIdx.x >> 4;
    float acc[4][4] = {};
    for (int s0 = 0; s0 < Tn; s0 += 16) {
#pragma unroll
        for (int i = 0; i < 4; i++) {
            int e = threadIdx.x + i*256;
            int m = e >> 4, kk = e & 15;
            Ps[kk][m] = Sp[(size_t)(t0 + m) * Tn + s0 + kk];
        }
#pragma unroll
        for (int i = 0; i < 4; i++) {
            int e = threadIdx.x + i*256;
            int kk = e >> 6, n = e & 63;
            Vs[kk][n] = Vp[(size_t)(s0 + kk) * Dm + n];
        }
        __syncthreads();
#pragma unroll
        for (int kk = 0; kk < 16; kk++) {
            float4 a4 = *(const float4*)&Ps[kk][ty*4];
            float4 b4 = *(const float4*)&Vs[kk][tx*4];
            float a[4] = {a4.x,a4.y,a4.z,a4.w};
            float b[4] = {b4.x,b4.y,b4.z,b4.w};
#pragma unroll
            for (int i = 0; i < 4; i++)
#pragma unroll
                for (int j = 0; j < 4; j++)
                    acc[i][j] = fmaf(a[i], b[j], acc[i][j]);
        }
        __syncthreads();
    }
    float* Op = O + (size_t)b*Tn*Dm + h*HSz;
#pragma unroll
    for (int i = 0; i < 4; i++)
#pragma unroll
        for (int j = 0; j < 4; j++)
            Op[(size_t)(t0 + ty*4 + i) * Dm + tx*4 + j] = acc[i][j];
}

// ---------------- loss -------------------------------------------------------

__global__ void k_lossrow(const float* __restrict__ logits, const int* __restrict__ tgt,
                          float* __restrict__ lr) {
    __shared__ float red[256];
    int row = blockIdx.x;
    const float* l = logits + (size_t)row * Vn;
    float mx = -1e38f;
    for (int c = threadIdx.x; c < Vn; c += 256) mx = fmaxf(mx, l[c]);
    red[threadIdx.x] = mx; __syncthreads();
    for (int off = 128; off > 0; off >>= 1) {
        if (threadIdx.x < off) red[threadIdx.x] = fmaxf(red[threadIdx.x], red[threadIdx.x+off]);
        __syncthreads();
    }
    mx = red[0]; __syncthreads();
    float s = 0.f;
    for (int c = threadIdx.x; c < Vn; c += 256) s += __expf(l[c] - mx);
    red[threadIdx.x] = s; __syncthreads();
    for (int off = 128; off > 0; off >>= 1) {
        if (threadIdx.x < off) red[threadIdx.x] += red[threadIdx.x+off];
        __syncthreads();
    }
    if (threadIdx.x == 0)
        lr[row] = mx + logf(red[0]) - l[tgt[row]];
}

__global__ void k_lossreduce(const float* __restrict__ lr, float* __restrict__ out) {
    __shared__ float red[256];
    float s = 0.f;
    for (int i = threadIdx.x; i < NT; i += 256) s += lr[i];
    red[threadIdx.x] = s; __syncthreads();
    for (int off = 128; off > 0; off >>= 1) {
        if (threadIdx.x < off) red[threadIdx.x] += red[threadIdx.x+off];
        __syncthreads();
    }
    if (threadIdx.x == 0) *out = red[0] / (float)NT;
}

// ---------------- host -------------------------------------------------------

extern "C" void kernel_launch(void* const* d_in, const int* in_sizes, int n_in,
                              void* d_out, int out_size) {
    const int*   idx  = (const int*)  d_in[0];
    const int*   tgt  = (const int*)  d_in[1];
    const float* tok  = (const float*)d_in[2];
    const float* pos  = (const float*)d_in[3];
    const float* uqw  = (const float*)d_in[4];
    const float* uqb  = (const float*)d_in[5];
    const float* upw  = (const float*)d_in[6];
    const float* upb  = (const float*)d_in[7];
    const float* mqw  = (const float*)d_in[8];
    const float* mqb  = (const float*)d_in[9];
    const float* mpw  = (const float*)d_in[10];
    const float* mpb  = (const float*)d_in[11];
    const float* w1   = (const float*)d_in[12];
    const float* b1   = (const float*)d_in[13];
    const float* w2   = (const float*)d_in[14];
    const float* b2   = (const float*)d_in[15];
    const float* g1   = (const float*)d_in[16];
    const float* bb1  = (const float*)d_in[17];
    const float* g2   = (const float*)d_in[18];
    const float* bb2  = (const float*)d_in[19];
    const float* lnfg = (const float*)d_in[20];
    const float* lnfb = (const float*)d_in[21];
    const float* wout = (const float*)d_in[22];
    const float* bout = (const float*)d_in[23];

    float *x, *x2, *xn, *qkv, *attn, *scores, *ff, *lr, *lfb;
    cudaGetSymbolAddress((void**)&x,      g_x);
    cudaGetSymbolAddress((void**)&x2,     g_x2);
    cudaGetSymbolAddress((void**)&xn,     g_xn);
    cudaGetSymbolAddress((void**)&qkv,    g_qkv);
    cudaGetSymbolAddress((void**)&attn,   g_attn);
    cudaGetSymbolAddress((void**)&scores, g_scores);
    cudaGetSymbolAddress((void**)&ff,     g_ff);
    cudaGetSymbolAddress((void**)&lr,     g_lossrow);
    cudaGetSymbolAddress((void**)&lfb,    g_logits_fb);

    k_embed<<<NT, 128>>>(idx, tok, pos, x);

    for (int l = 0; l < Lnum; l++) {
        for (int half = 0; half < 2; half++) {
            const float* qw = (half == 0 ? uqw : mqw) + (size_t)l * 3 * Dm * Dm;
            const float* qb = (half == 0 ? uqb : mqb) + (size_t)l * 3 * Dm;
            const float* pw = (half == 0 ? upw : mpw) + (size_t)l * Dm * Dm;
            const float* pb = (half == 0 ? upb : mpb) + (size_t)l * Dm;
            int causal = half;

            // x2 = x + MHA(LN1(x))
            k_layernorm<<<NT, 128>>>(x, g1 + (size_t)l*Dm, bb1 + (size_t)l*Dm, xn);
            // merged Q,K,V via grid.z
            k_gemm_small<<<dim3(Dm/64, NT/64, 3), 128>>>(
                xn, qw, qb, nullptr, qkv, NT, Dm, Dm,
                (long long)Dm*Dm, (long long)Dm, (long long)NT*Dm);
            k_attn_scores<<<dim3(Tn/64, Tn/64, Bsz*Hn), 256>>>(qkv, scores, causal);
            k_softmax<<<Bsz*Hn*Tn, 128>>>(scores);
            k_attn_pv<<<dim3(Tn/64, Bsz*Hn), 256>>>(scores, qkv, attn);
            k_gemm_small<<<dim3(Dm/64, NT/64, 1), 128>>>(
                attn, pw, pb, x, x2, NT, Dm, Dm, 0, 0, 0);

            // x = x2 + FF(LN2(x2))
            k_layernorm<<<NT, 128>>>(x2, g2 + (size_t)l*Dm, bb2 + (size_t)l*Dm, xn);
            k_gemm_big<<<dim3(DFn/128, NT/128), 256>>>(
                xn, w1 + (size_t)l*Dm*DFn, b1 + (size_t)l*DFn, ff,
                NT, DFn, Dm, /*gelu=*/1);
            k_gemm_small<<<dim3(Dm/64, NT/64, 1), 128>>>(
                ff, w2 + (size_t)l*DFn*Dm, b2 + (size_t)l*Dm, x2, x,
                NT, Dm, DFn, 0, 0, 0);
        }
    }

    // final LN + logits + loss
    k_layernorm<<<NT, 128>>>(x, lnfg, lnfb, xn);

    long long total = (long long)NT * Vn;
    float* logits = ((long long)out_size >= total) ? (float*)d_out : lfb;
    k_gemm_big<<<dim3(Vn/128, NT/128), 256>>>(xn, wout, bout, logits,
                                              NT, Vn, Dm, /*gelu=*/0);

    k_lossrow<<<NT, 256>>>(logits, tgt, lr);

    float* lossdst;
    if ((long long)out_size >= total + 1)      lossdst = (float*)d_out + total;
    else if ((long long)out_size < total)      lossdst = (float*)d_out;
    else                                       lossdst = lr;
    k_lossreduce<<<1, 256>>>(lr, lossdst);
}

// round 8
// speedup vs baseline: 1.2410x; 1.1803x over previous
#include <cuda_runtime.h>
#include <cuda_bf16.h>
#include <math.h>
#include <stdint.h>

#define Bsz 4
#define Tn  512
#define Dm  512
#define Hn  8
#define HSz 64
#define Lnum 8
#define Vn  32000
#define DFn 2048
#define NT  (Bsz*Tn)
#define EPSf 1e-5f
#define K3D (3*Dm)     // 1536
#define K3F (3*DFn)    // 6144

// ---------------- scratch ----------------------------------------------------
__device__ float g_x [NT*Dm];
__device__ float g_x2[NT*Dm];
__device__ float g_qkv[3*NT*Dm];
__device__ float g_scores[(size_t)Bsz*Hn*Tn*Tn];
__device__ float g_lossrow[NT];
__device__ float g_lfb[(size_t)NT*Vn];

// bf16 triple-split activations
__device__ __nv_bfloat16 g_xn3 [NT*K3D];
__device__ __nv_bfloat16 g_at3 [NT*K3D];
__device__ __nv_bfloat16 g_ff3 [NT*K3F];

// bf16 triple-split weights (converted every launch)
__device__ __nv_bfloat16 g_w3_uqkv [Lnum*3*K3D*Dm];
__device__ __nv_bfloat16 g_w3_mqkv [Lnum*3*K3D*Dm];
__device__ __nv_bfloat16 g_w3_uproj[Lnum*K3D*Dm];
__device__ __nv_bfloat16 g_w3_mproj[Lnum*K3D*Dm];
__device__ __nv_bfloat16 g_w3_w1   [Lnum*K3D*DFn];
__device__ __nv_bfloat16 g_w3_w2   [Lnum*K3F*Dm];
__device__ __nv_bfloat16 g_w3_wout [K3D*Vn];

// ---------------- helpers ----------------------------------------------------

__device__ __forceinline__ float gelu_f(float v) {
    return 0.5f * v * (1.f + erff(v * 0.70710678118654752f));
}

// write [hi, hi, lo] triple
__device__ __forceinline__ void store3(__nv_bfloat16* p, float v) {
    __nv_bfloat16 h = __float2bfloat16_rn(v);
    __nv_bfloat16 l = __float2bfloat16_rn(v - __bfloat162float(h));
    p[0] = h; p[1] = h; p[2] = l;
}

__device__ __forceinline__ void ldsm_x4(uint32_t& r0, uint32_t& r1, uint32_t& r2,
                                        uint32_t& r3, const void* p) {
    uint32_t a = (uint32_t)__cvta_generic_to_shared(p);
    asm volatile("ldmatrix.sync.aligned.m8n8.x4.shared.b16 {%0,%1,%2,%3}, [%4];"
                 : "=r"(r0), "=r"(r1), "=r"(r2), "=r"(r3) : "r"(a));
}
__device__ __forceinline__ void ldsm_x4t(uint32_t& r0, uint32_t& r1, uint32_t& r2,
                                         uint32_t& r3, const void* p) {
    uint32_t a = (uint32_t)__cvta_generic_to_shared(p);
    asm volatile("ldmatrix.sync.aligned.m8n8.x4.trans.shared.b16 {%0,%1,%2,%3}, [%4];"
                 : "=r"(r0), "=r"(r1), "=r"(r2), "=r"(r3) : "r"(a));
}
__device__ __forceinline__ void mma16816(float* c, const uint32_t* a, const uint32_t* b) {
    asm volatile("mma.sync.aligned.m16n8k16.row.col.f32.bf16.bf16.f32 "
                 "{%0,%1,%2,%3},{%4,%5,%6,%7},{%8,%9},{%0,%1,%2,%3};"
                 : "+f"(c[0]), "+f"(c[1]), "+f"(c[2]), "+f"(c[3])
                 : "r"(a[0]), "r"(a[1]), "r"(a[2]), "r"(a[3]), "r"(b[0]), "r"(b[1]));
}

// ---------------- weight conversion ------------------------------------------
// W[K][N] fp32 -> out[3K][N] bf16 rows [hi, lo, hi]
__global__ void k_cvt_w(const float* __restrict__ W, __nv_bfloat16* __restrict__ out,
                        int K, int N, long long inz, long long outz) {
    const float* Wp = W + (size_t)blockIdx.z * inz;
    __nv_bfloat16* op = out + (size_t)blockIdx.z * outz;
    long long total = (long long)K * N;
    for (long long i = (long long)blockIdx.x * blockDim.x + threadIdx.x; i < total;
         i += (long long)gridDim.x * blockDim.x) {
        int k = (int)(i / N), n = (int)(i % N);
        float v = Wp[i];
        __nv_bfloat16 h = __float2bfloat16_rn(v);
        __nv_bfloat16 l = __float2bfloat16_rn(v - __bfloat162float(h));
        op[(size_t)(3*k+0)*N + n] = h;
        op[(size_t)(3*k+1)*N + n] = l;
        op[(size_t)(3*k+2)*N + n] = h;
    }
}

// ---------------- tensor-core GEMM -------------------------------------------
// C[M,N] = A3[M,K3] @ W3[K3,N]  (bf16 x bf16 -> fp32), K3 = 3*K_logical.
// BM = MT*32 (MT=4 ->128, MT=2 ->64), BN = 128, BK = 32. 256 threads, 8 warps (2x4).
template<int MT>
__global__ void __launch_bounds__(256) k_mma(
    const __nv_bfloat16* __restrict__ A3, const __nv_bfloat16* __restrict__ W3,
    const float* __restrict__ bias, const float* __restrict__ res,
    float* __restrict__ outF, __nv_bfloat16* __restrict__ out3,
    int N, int K3, long long wz, long long bz, long long cz, int gelu) {
    constexpr int BM = MT * 32;
    constexpr int NA = (BM * 32) / (256 * 8);
    __shared__ __nv_bfloat16 As[2][BM][40];
    __shared__ __nv_bfloat16 Bs[2][32][136];

    if (wz) {
        W3   += (size_t)blockIdx.z * wz;
        bias += (size_t)blockIdx.z * bz;
        outF += (size_t)blockIdx.z * cz;
    }
    int tid = threadIdx.x, lane = tid & 31, warp = tid >> 5;
    int wm = warp >> 2, wn = warp & 3;
    int bm = blockIdx.y * BM, bn = blockIdx.x * 128;

    float acc[MT][4][4];
#pragma unroll
    for (int i = 0; i < MT; i++)
#pragma unroll
        for (int j = 0; j < 4; j++)
#pragma unroll
            for (int k = 0; k < 4; k++) acc[i][j][k] = 0.f;

    uint4 ra[NA], rb[2];
    // prologue: k0 = 0
#pragma unroll
    for (int i = 0; i < NA; i++) {
        int id = tid + i*256;
        ra[i] = *(const uint4*)(A3 + (size_t)(bm + (id >> 2)) * K3 + (id & 3) * 8);
    }
#pragma unroll
    for (int i = 0; i < 2; i++) {
        int id = tid + i*256;
        rb[i] = *(const uint4*)(W3 + (size_t)(id >> 4) * N + bn + (id & 15) * 8);
    }
#pragma unroll
    for (int i = 0; i < NA; i++) {
        int id = tid + i*256;
        *(uint4*)&As[0][id >> 2][(id & 3) * 8] = ra[i];
    }
#pragma unroll
    for (int i = 0; i < 2; i++) {
        int id = tid + i*256;
        *(uint4*)&Bs[0][id >> 4][(id & 15) * 8] = rb[i];
    }
    __syncthreads();

    int KT = K3 / 32;
    for (int t = 0; t < KT; t++) {
        int buf = t & 1;
        if (t + 1 < KT) {
            int k0 = (t + 1) * 32;
#pragma unroll
            for (int i = 0; i < NA; i++) {
                int id = tid + i*256;
                ra[i] = *(const uint4*)(A3 + (size_t)(bm + (id >> 2)) * K3 + k0 + (id & 3) * 8);
            }
#pragma unroll
            for (int i = 0; i < 2; i++) {
                int id = tid + i*256;
                rb[i] = *(const uint4*)(W3 + (size_t)(k0 + (id >> 4)) * N + bn + (id & 15) * 8);
            }
        }
#pragma unroll
        for (int kh = 0; kh < 2; kh++) {
            int k16 = kh * 16;
            uint32_t a[MT][4];
#pragma unroll
            for (int mt = 0; mt < MT; mt++)
                ldsm_x4(a[mt][0], a[mt][1], a[mt][2], a[mt][3],
                        &As[buf][wm*MT*16 + mt*16 + (lane & 15)][k16 + ((lane >> 4) << 3)]);
            uint32_t b[4][2];
#pragma unroll
            for (int h2 = 0; h2 < 2; h2++) {
                uint32_t r0, r1, r2, r3;
                ldsm_x4t(r0, r1, r2, r3,
                         &Bs[buf][k16 + (lane & 15)][wn*32 + h2*16 + ((lane >> 4) << 3)]);
                b[h2*2][0] = r0; b[h2*2][1] = r1;
                b[h2*2+1][0] = r2; b[h2*2+1][1] = r3;
            }
#pragma unroll
            for (int mt = 0; mt < MT; mt++)
#pragma unroll
                for (int nt = 0; nt < 4; nt++)
                    mma16816(acc[mt][nt], a[mt], b[nt]);
        }
        if (t + 1 < KT) {
            int nb = (t + 1) & 1;
#pragma unroll
            for (int i = 0; i < NA; i++) {
                int id = tid + i*256;
                *(uint4*)&As[nb][id >> 2][(id & 3) * 8] = ra[i];
            }
#pragma unroll
            for (int i = 0; i < 2; i++) {
                int id = tid + i*256;
                *(uint4*)&Bs[nb][id >> 4][(id & 15) * 8] = rb[i];
            }
            __syncthreads();
        }
    }

    // epilogue
    int r = lane >> 2, cg = lane & 3;
#pragma unroll
    for (int mt = 0; mt < MT; mt++) {
        int row0 = bm + wm*MT*16 + mt*16 + r;
        int row1 = row0 + 8;
#pragma unroll
        for (int nt = 0; nt < 4; nt++) {
            int col = bn + wn*32 + nt*8 + cg*2;
            float v00 = acc[mt][nt][0] + bias[col];
            float v01 = acc[mt][nt][1] + bias[col+1];
            float v10 = acc[mt][nt][2] + bias[col];
            float v11 = acc[mt][nt][3] + bias[col+1];
            if (gelu) { v00 = gelu_f(v00); v01 = gelu_f(v01);
                        v10 = gelu_f(v10); v11 = gelu_f(v11); }
            if (res) {
                float2 r0 = *(const float2*)&res[(size_t)row0*N + col];
                float2 r1 = *(const float2*)&res[(size_t)row1*N + col];
                v00 += r0.x; v01 += r0.y; v10 += r1.x; v11 += r1.y;
            }
            if (outF) {
                *(float2*)&outF[(size_t)row0*N + col] = make_float2(v00, v01);
                *(float2*)&outF[(size_t)row1*N + col] = make_float2(v10, v11);
            }
            if (out3) {
                store3(out3 + (size_t)row0*3*N + 3*col,     v00);
                store3(out3 + (size_t)row0*3*N + 3*(col+1), v01);
                store3(out3 + (size_t)row1*3*N + 3*col,     v10);
                store3(out3 + (size_t)row1*3*N + 3*(col+1), v11);
            }
        }
    }
}

// ---------------- non-GEMM kernels -------------------------------------------

__global__ void k_embed(const int* __restrict__ idx, const float* __restrict__ tok,
                        const float* __restrict__ pos, float* __restrict__ x) {
    int row = blockIdx.x;
    int t = row % Tn;
    int tk = idx[row];
    const float* te = tok + (size_t)tk * Dm;
    const float* pe = pos + (size_t)t  * Dm;
    float* xr = x + (size_t)row * Dm;
    for (int c = threadIdx.x; c < Dm; c += blockDim.x)
        xr[c] = te[c] + pe[c];
}

// LayerNorm -> bf16 triple output
__global__ void k_layernorm3(const float* __restrict__ x, const float* __restrict__ g,
                             const float* __restrict__ b, __nv_bfloat16* __restrict__ y3) {
    __shared__ float s1[128], s2[128];
    int row = blockIdx.x;
    const float* xr = x + (size_t)row * Dm;
    __nv_bfloat16* yr = y3 + (size_t)row * K3D;
    float v[4], sum = 0.f, sq = 0.f;
#pragma unroll
    for (int i = 0; i < 4; i++) {
        v[i] = xr[threadIdx.x + i*128];
        sum += v[i]; sq += v[i]*v[i];
    }
    s1[threadIdx.x] = sum; s2[threadIdx.x] = sq; __syncthreads();
    for (int off = 64; off > 0; off >>= 1) {
        if (threadIdx.x < off) { s1[threadIdx.x] += s1[threadIdx.x+off];
                                 s2[threadIdx.x] += s2[threadIdx.x+off]; }
        __syncthreads();
    }
    float mu  = s1[0] * (1.f/Dm);
    float var = s2[0] * (1.f/Dm) - mu*mu;
    float rstd = rsqrtf(var + EPSf);
#pragma unroll
    for (int i = 0; i < 4; i++) {
        int c = threadIdx.x + i*128;
        store3(yr + 3*c, (v[i] - mu) * rstd * g[c] + b[c]);
    }
}

__global__ __launch_bounds__(256) void k_attn_scores(
    const float* __restrict__ qkv, float* __restrict__ S, int causal) {
    int bh = blockIdx.z, b = bh >> 3, h = bh & 7;
    int t0 = blockIdx.y * 64, s0 = blockIdx.x * 64;
    __shared__ float Qs[64][68], Ks[64][68];
    const float* Q  = qkv + (size_t)(b*Tn + t0) * Dm + h*HSz;
    const float* Kp = qkv + (size_t)NT*Dm + (size_t)(b*Tn + s0) * Dm + h*HSz;
    int tid = threadIdx.x;
#pragma unroll
    for (int i = 0; i < 4; i++) {
        int p = tid + i*256;
        int rr = p >> 4, c4 = (p & 15) * 4;
        float4 q = *(const float4*)&Q [(size_t)rr * Dm + c4];
        float4 k = *(const float4*)&Kp[(size_t)rr * Dm + c4];
        Qs[c4+0][rr]=q.x; Qs[c4+1][rr]=q.y; Qs[c4+2][rr]=q.z; Qs[c4+3][rr]=q.w;
        Ks[c4+0][rr]=k.x; Ks[c4+1][rr]=k.y; Ks[c4+2][rr]=k.z; Ks[c4+3][rr]=k.w;
    }
    __syncthreads();
    int tx = tid & 15, ty = tid >> 4;
    float acc[4][4] = {};
#pragma unroll
    for (int kk = 0; kk < 64; kk++) {
        float4 a4 = *(const float4*)&Qs[kk][ty*4];
        float4 b4 = *(const float4*)&Ks[kk][tx*4];
        float a[4] = {a4.x,a4.y,a4.z,a4.w};
        float b[4] = {b4.x,b4.y,b4.z,b4.w};
#pragma unroll
        for (int i = 0; i < 4; i++)
#pragma unroll
            for (int j = 0; j < 4; j++)
                acc[i][j] = fmaf(a[i], b[j], acc[i][j]);
    }
    float* Sp = S + (size_t)bh * Tn * Tn;
#pragma unroll
    for (int i = 0; i < 4; i++) {
        int t = t0 + ty*4 + i;
#pragma unroll
        for (int j = 0; j < 4; j++) {
            int s = s0 + tx*4 + j;
            float v = acc[i][j] * 0.125f;
            if (causal && s > t) v = -1e30f;
            Sp[(size_t)t * Tn + s] = v;
        }
    }
}

__global__ void k_softmax(float* __restrict__ S) {
    __shared__ float red[128];
    int row = blockIdx.x;
    float* r = S + (size_t)row * Tn;
    float v[4], mx = -1e38f;
#pragma unroll
    for (int i = 0; i < 4; i++) { v[i] = r[threadIdx.x + i*128]; mx = fmaxf(mx, v[i]); }
    red[threadIdx.x] = mx; __syncthreads();
    for (int off = 64; off > 0; off >>= 1) {
        if (threadIdx.x < off) red[threadIdx.x] = fmaxf(red[threadIdx.x], red[threadIdx.x+off]);
        __syncthreads();
    }
    mx = red[0]; __syncthreads();
    float s = 0.f;
#pragma unroll
    for (int i = 0; i < 4; i++) { v[i] = __expf(v[i] - mx); s += v[i]; }
    red[threadIdx.x] = s; __syncthreads();
    for (int off = 64; off > 0; off >>= 1) {
        if (threadIdx.x < off) red[threadIdx.x] += red[threadIdx.x+off];
        __syncthreads();
    }
    float inv = 1.f / red[0];
#pragma unroll
    for (int i = 0; i < 4; i++) r[threadIdx.x + i*128] = v[i] * inv;
}

// PV -> bf16 triple output (feeds proj GEMM)
__global__ __launch_bounds__(256) void k_attn_pv3(
    const float* __restrict__ S, const float* __restrict__ qkv,
    __nv_bfloat16* __restrict__ O3) {
    int bh = blockIdx.y, b = bh >> 3, h = bh & 7;
    int t0 = blockIdx.x * 64;
    __shared__ float Ps[16][68];
    __shared__ float Vs[16][68];
    const float* Sp = S + (size_t)bh * Tn * Tn;
    const float* Vp = qkv + (size_t)2*NT*Dm + (size_t)b*Tn*Dm + h*HSz;
    int tx = threadIdx.x & 15, ty = threadIdx.x >> 4;
    float acc[4][4] = {};
    for (int s0 = 0; s0 < Tn; s0 += 16) {
#pragma unroll
        for (int i = 0; i < 4; i++) {
            int e = threadIdx.x + i*256;
            int m = e >> 4, kk = e & 15;
            Ps[kk][m] = Sp[(size_t)(t0 + m) * Tn + s0 + kk];
        }
#pragma unroll
        for (int i = 0; i < 4; i++) {
            int e = threadIdx.x + i*256;
            int kk = e >> 6, n = e & 63;
            Vs[kk][n] = Vp[(size_t)(s0 + kk) * Dm + n];
        }
        __syncthreads();
#pragma unroll
        for (int kk = 0; kk < 16; kk++) {
            float4 a4 = *(const float4*)&Ps[kk][ty*4];
            float4 b4 = *(const float4*)&Vs[kk][tx*4];
            float a[4] = {a4.x,a4.y,a4.z,a4.w};
            float b[4] = {b4.x,b4.y,b4.z,b4.w};
#pragma unroll
            for (int i = 0; i < 4; i++)
#pragma unroll
                for (int j = 0; j < 4; j++)
                    acc[i][j] = fmaf(a[i], b[j], acc[i][j]);
        }
        __syncthreads();
    }
#pragma unroll
    for (int i = 0; i < 4; i++) {
        int row = b*Tn + t0 + ty*4 + i;
#pragma unroll
        for (int j = 0; j < 4; j++) {
            int col = h*HSz + tx*4 + j;
            store3(O3 + (size_t)row*K3D + 3*col, acc[i][j]);
        }
    }
}

__global__ void k_lossrow(const float* __restrict__ logits, const int* __restrict__ tgt,
                          float* __restrict__ lr) {
    __shared__ float red[256];
    int row = blockIdx.x;
    const float* l = logits + (size_t)row * Vn;
    float mx = -1e38f;
    for (int c = threadIdx.x; c < Vn; c += 256) mx = fmaxf(mx, l[c]);
    red[threadIdx.x] = mx; __syncthreads();
    for (int off = 128; off > 0; off >>= 1) {
        if (threadIdx.x < off) red[threadIdx.x] = fmaxf(red[threadIdx.x], red[threadIdx.x+off]);
        __syncthreads();
    }
    mx = red[0]; __syncthreads();
    float s = 0.f;
    for (int c = threadIdx.x; c < Vn; c += 256) s += __expf(l[c] - mx);
    red[threadIdx.x] = s; __syncthreads();
    for (int off = 128; off > 0; off >>= 1) {
        if (threadIdx.x < off) red[threadIdx.x] += red[threadIdx.x+off];
        __syncthreads();
    }
    if (threadIdx.x == 0)
        lr[row] = mx + logf(red[0]) - l[tgt[row]];
}

__global__ void k_lossreduce(const float* __restrict__ lr, float* __restrict__ out) {
    __shared__ float red[256];
    float s = 0.f;
    for (int i = threadIdx.x; i < NT; i += 256) s += lr[i];
    red[threadIdx.x] = s; __syncthreads();
    for (int off = 128; off > 0; off >>= 1) {
        if (threadIdx.x < off) red[threadIdx.x] += red[threadIdx.x+off];
        __syncthreads();
    }
    if (threadIdx.x == 0) *out = red[0] / (float)NT;
}

// ---------------- host -------------------------------------------------------

extern "C" void kernel_launch(void* const* d_in, const int* in_sizes, int n_in,
                              void* d_out, int out_size) {
    const int*   idx  = (const int*)  d_in[0];
    const int*   tgt  = (const int*)  d_in[1];
    const float* tok  = (const float*)d_in[2];
    const float* pos  = (const float*)d_in[3];
    const float* uqw  = (const float*)d_in[4];
    const float* uqb  = (const float*)d_in[5];
    const float* upw  = (const float*)d_in[6];
    const float* upb  = (const float*)d_in[7];
    const float* mqw  = (const float*)d_in[8];
    const float* mqb  = (const float*)d_in[9];
    const float* mpw  = (const float*)d_in[10];
    const float* mpb  = (const float*)d_in[11];
    const float* w1   = (const float*)d_in[12];
    const float* b1   = (const float*)d_in[13];
    const float* w2   = (const float*)d_in[14];
    const float* b2   = (const float*)d_in[15];
    const float* g1   = (const float*)d_in[16];
    const float* bb1  = (const float*)d_in[17];
    const float* g2   = (const float*)d_in[18];
    const float* bb2  = (const float*)d_in[19];
    const float* lnfg = (const float*)d_in[20];
    const float* lnfb = (const float*)d_in[21];
    const float* wout = (const float*)d_in[22];
    const float* bout = (const float*)d_in[23];

    float *x, *x2, *qkv, *scores, *lr, *lfb;
    __nv_bfloat16 *xn3, *at3, *ff3;
    __nv_bfloat16 *wuq, *wmq, *wup, *wmp, *ww1, *ww2, *wwo;
    cudaGetSymbolAddress((void**)&x,      g_x);
    cudaGetSymbolAddress((void**)&x2,     g_x2);
    cudaGetSymbolAddress((void**)&qkv,    g_qkv);
    cudaGetSymbolAddress((void**)&scores, g_scores);
    cudaGetSymbolAddress((void**)&lr,     g_lossrow);
    cudaGetSymbolAddress((void**)&lfb,    g_lfb);
    cudaGetSymbolAddress((void**)&xn3,    g_xn3);
    cudaGetSymbolAddress((void**)&at3,    g_at3);
    cudaGetSymbolAddress((void**)&ff3,    g_ff3);
    cudaGetSymbolAddress((void**)&wuq,    g_w3_uqkv);
    cudaGetSymbolAddress((void**)&wmq,    g_w3_mqkv);
    cudaGetSymbolAddress((void**)&wup,    g_w3_uproj);
    cudaGetSymbolAddress((void**)&wmp,    g_w3_mproj);
    cudaGetSymbolAddress((void**)&ww1,    g_w3_w1);
    cudaGetSymbolAddress((void**)&ww2,    g_w3_w2);
    cudaGetSymbolAddress((void**)&wwo,    g_w3_wout);

    // ---- weight conversion (every launch; ~0.1ms) ----
    k_cvt_w<<<dim3(512, 1, Lnum*3), 256>>>(uqw, wuq, Dm, Dm,
        (long long)Dm*Dm, (long long)K3D*Dm);
    k_cvt_w<<<dim3(512, 1, Lnum*3), 256>>>(mqw, wmq, Dm, Dm,
        (long long)Dm*Dm, (long long)K3D*Dm);
    k_cvt_w<<<dim3(512, 1, Lnum), 256>>>(upw, wup, Dm, Dm,
        (long long)Dm*Dm, (long long)K3D*Dm);
    k_cvt_w<<<dim3(512, 1, Lnum), 256>>>(mpw, wmp, Dm, Dm,
        (long long)Dm*Dm, (long long)K3D*Dm);
    k_cvt_w<<<dim3(2048, 1, Lnum), 256>>>(w1, ww1, Dm, DFn,
        (long long)Dm*DFn, (long long)K3D*DFn);
    k_cvt_w<<<dim3(2048, 1, Lnum), 256>>>(w2, ww2, DFn, Dm,
        (long long)DFn*Dm, (long long)K3F*Dm);
    k_cvt_w<<<dim3(16384, 1, 1), 256>>>(wout, wwo, Dm, Vn, 0, 0);

    k_embed<<<NT, 128>>>(idx, tok, pos, x);

    for (int l = 0; l < Lnum; l++) {
        for (int half = 0; half < 2; half++) {
            const __nv_bfloat16* qw3 = (half == 0 ? wuq : wmq) + (size_t)l * 3 * K3D * Dm;
            const __nv_bfloat16* pw3 = (half == 0 ? wup : wmp) + (size_t)l * K3D * Dm;
            const float* qb = (half == 0 ? uqb : mqb) + (size_t)l * 3 * Dm;
            const float* pb = (half == 0 ? upb : mpb) + (size_t)l * Dm;
            int causal = half;

            // x2 = x + MHA(LN1(x))
            k_layernorm3<<<NT, 128>>>(x, g1 + (size_t)l*Dm, bb1 + (size_t)l*Dm, xn3);
            k_mma<2><<<dim3(Dm/128, NT/64, 3), 256>>>(
                xn3, qw3, qb, nullptr, qkv, nullptr, Dm, K3D,
                (long long)K3D*Dm, (long long)Dm, (long long)NT*Dm, 0);
            k_attn_scores<<<dim3(Tn/64, Tn/64, Bsz*Hn), 256>>>(qkv, scores, causal);
            k_softmax<<<Bsz*Hn*Tn, 128>>>(scores);
            k_attn_pv3<<<dim3(Tn/64, Bsz*Hn), 256>>>(scores, qkv, at3);
            k_mma<2><<<dim3(Dm/128, NT/64, 1), 256>>>(
                at3, pw3, pb, x, x2, nullptr, Dm, K3D, 0, 0, 0, 0);

            // x = x2 + FF(LN2(x2))
            k_layernorm3<<<NT, 128>>>(x2, g2 + (size_t)l*Dm, bb2 + (size_t)l*Dm, xn3);
            k_mma<4><<<dim3(DFn/128, NT/128, 1), 256>>>(
                xn3, ww1 + (size_t)l*K3D*DFn, b1 + (size_t)l*DFn, nullptr,
                nullptr, ff3, DFn, K3D, 0, 0, 0, 1);
            k_mma<2><<<dim3(Dm/128, NT/64, 1), 256>>>(
                ff3, ww2 + (size_t)l*K3F*Dm, b2 + (size_t)l*Dm, x2, x, nullptr,
                Dm, K3F, 0, 0, 0, 0);
        }
    }

    // final LN + logits + loss
    k_layernorm3<<<NT, 128>>>(x, lnfg, lnfb, xn3);

    long long total = (long long)NT * Vn;
    float* logits = ((long long)out_size >= total) ? (float*)d_out : lfb;
    k_mma<4><<<dim3(Vn/128, NT/128, 1), 256>>>(
        xn3, wwo, bout, nullptr, logits, nullptr, Vn, K3D, 0, 0, 0, 0);

    k_lossrow<<<NT, 256>>>(logits, tgt, lr);

    float* lossdst;
    if ((long long)out_size >= total + 1)      lossdst = (float*)d_out + total;
    else if ((long long)out_size < total)      lossdst = (float*)d_out;
    else                                       lossdst = lr;
    k_lossreduce<<<1, 256>>>(lr, lossdst);
}